// round 7
// baseline (speedup 1.0000x reference)
#include <cuda_runtime.h>
#include <cuda_fp16.h>
#include <mma.h>
#include <cstdint>
using namespace nvcuda;

#define NB 2
#define L 6400
#define S 6400
#define C 256
#define GRID_W 80
#define BORDER 2

static constexpr float SIM_SCALE = 1.0f / 25.6f;   // 1/(C*TEMPERATURE)
static constexpr float THRESH = 0.2f;
static constexpr long long NLS = (long long)NB * L * S;

#define BM 128
#define BN 128
#define BK 32
#define NKT (C / BK)            // 8
#define STAGES 3
#define SSTR 48                 // smem half stride (96B rows)
#define STAGE_STRIDE 132        // floats
#define TILE_BYTES ((BM + BN) * SSTR * 2)      // 24576 per stage
#define SMEM_BYTES (STAGES * TILE_BYTES)       // 73728 >= stage overlay (67584)

// ---- scratch (static __device__ globals: allowed) ----
__device__ __align__(16) __half g_h0[NB * L * C];
__device__ __align__(16) __half g_h1[NB * S * C];
__device__ __align__(16) __half g_Eh[NB * L * S];   // 164 MB fp16 exp(sim)
__device__ float g_rowsum[NB * L];
__device__ float g_colsum[NB * S];
__device__ float g_rowmax[NB * L];
__device__ int   g_rowarg[NB * L];
__device__ int   g_colmax[NB * S];   // float bits; conf > 0 so int order == float order

// ---------------------------------------------------------------------------
__device__ __forceinline__ uint32_t smem_u32(const void* p) {
    uint32_t a;
    asm("{ .reg .u64 t; cvta.to.shared.u64 t, %1; cvt.u32.u64 %0, t; }" : "=r"(a) : "l"(p));
    return a;
}
__device__ __forceinline__ void cp_async16(uint32_t saddr, const void* gaddr) {
    asm volatile("cp.async.cg.shared.global [%0], [%1], 16;" :: "r"(saddr), "l"(gaddr));
}
#define CP_COMMIT() asm volatile("cp.async.commit_group;" ::: "memory")
#define CP_WAIT(n)  asm volatile("cp.async.wait_group %0;" :: "n"(n) : "memory")

// ---------------------------------------------------------------------------
// 0) float -> half conversion + stats zeroing (fused; runs every replay)
// ---------------------------------------------------------------------------
#define CVT_CHUNKS (NB * L * C / 4)
__global__ __launch_bounds__(256) void cvt_k(const float4* __restrict__ x0,
                                             const float4* __restrict__ x1) {
    int i = blockIdx.x * blockDim.x + threadIdx.x;
    if (i < NB * S) { g_colsum[i] = 0.0f; g_colmax[i] = 0; g_rowsum[i] = 0.0f; }
    if (i < CVT_CHUNKS) {
        float4 v = x0[i];
        __half2* o = (__half2*)g_h0;
        o[2 * i]     = __floats2half2_rn(v.x, v.y);
        o[2 * i + 1] = __floats2half2_rn(v.z, v.w);
    } else if (i < 2 * CVT_CHUNKS) {
        int j = i - CVT_CHUNKS;
        float4 v = x1[j];
        __half2* o = (__half2*)g_h1;
        o[2 * j]     = __floats2half2_rn(v.x, v.y);
        o[2 * j + 1] = __floats2half2_rn(v.z, v.w);
    }
}

// ---------------------------------------------------------------------------
// 1) FP16 WMMA GEMM 128x128, 3-stage cp.async, fused exp + sums, E as fp16
// ---------------------------------------------------------------------------
__global__ __launch_bounds__(256, 2) void gemm_exp_k() {
    extern __shared__ char smem[];
    const uint32_t sb = smem_u32(smem);
    float* stage = (float*)smem;        // overlays stage buffers after mainloop

    const int t = threadIdx.x;
    const int wid = t >> 5;
    const int wm = wid >> 2;       // 0..1 -> 64 rows
    const int wn = wid & 3;        // 0..3 -> 32 cols
    const int n = blockIdx.z;
    const int l0 = blockIdx.y * BM, s0 = blockIdx.x * BN;

    const __half* A = g_h0 + (size_t)n * L * C;
    const __half* B = g_h1 + (size_t)n * S * C;
    __half* Eo = g_Eh + (size_t)n * L * S;

    wmma::fragment<wmma::accumulator, 16, 16, 16, float> acc[4][2];
    #pragma unroll
    for (int i = 0; i < 4; i++)
        #pragma unroll
        for (int j = 0; j < 2; j++)
            wmma::fill_fragment(acc[i][j], 0.0f);

    auto load_tile = [&](int kt) {
        const int k0 = kt * BK;
        const uint32_t st = (kt % STAGES) * TILE_BYTES;
        #pragma unroll
        for (int i = 0; i < 2; i++) {
            int c = t + i * 256;               // 0..511
            int r = c >> 2, u = c & 3;
            uint32_t so = st + (uint32_t)(r * SSTR + u * 8) * 2;
            cp_async16(sb + so, A + (size_t)(l0 + r) * C + k0 + u * 8);
            cp_async16(sb + so + BM * SSTR * 2, B + (size_t)(s0 + r) * C + k0 + u * 8);
        }
        CP_COMMIT();
    };

    load_tile(0);
    load_tile(1);

    for (int kt = 0; kt < NKT; kt++) {
        CP_WAIT(1);
        __syncthreads();
        if (kt + 2 < NKT) load_tile(kt + 2);
        else              CP_COMMIT();

        const __half* Ab = (const __half*)(smem + (kt % STAGES) * TILE_BYTES);
        const __half* Bb = Ab + BM * SSTR;
        #pragma unroll
        for (int ks = 0; ks < BK; ks += 16) {
            wmma::fragment<wmma::matrix_a, 16, 16, 16, __half, wmma::row_major> af[4];
            wmma::fragment<wmma::matrix_b, 16, 16, 16, __half, wmma::col_major> bf[2];
            #pragma unroll
            for (int i = 0; i < 4; i++)
                wmma::load_matrix_sync(af[i], Ab + (wm * 64 + i * 16) * SSTR + ks, SSTR);
            #pragma unroll
            for (int j = 0; j < 2; j++)
                wmma::load_matrix_sync(bf[j], Bb + (wn * 32 + j * 16) * SSTR + ks, SSTR);
            #pragma unroll
            for (int i = 0; i < 4; i++)
                #pragma unroll
                for (int j = 0; j < 2; j++)
                    wmma::mma_sync(acc[i][j], af[i], bf[j], acc[i][j]);
        }
    }
    __syncthreads();

    // ---- epilogue: exp, stage, row/col partial sums, coalesced fp16 store
    #pragma unroll
    for (int i = 0; i < 4; i++) {
        #pragma unroll
        for (int j = 0; j < 2; j++) {
            #pragma unroll
            for (int e = 0; e < acc[i][j].num_elements; e++)
                acc[i][j].x[e] = __expf(acc[i][j].x[e] * SIM_SCALE);
            wmma::store_matrix_sync(
                &stage[(size_t)(wm * 64 + i * 16) * STAGE_STRIDE + wn * 32 + j * 16],
                acc[i][j], STAGE_STRIDE, wmma::mem_row_major);
        }
    }
    __syncthreads();

    {   // row partial sums
        const int r = t & 127, h = t >> 7;
        float s = 0.0f;
        #pragma unroll 16
        for (int c = 0; c < 64; c++) s += stage[r * STAGE_STRIDE + h * 64 + c];
        atomicAdd(&g_rowsum[n * L + l0 + r], s);
    }
    {   // col partial sums
        const int c = t & 127, h = t >> 7;
        float s = 0.0f;
        #pragma unroll 16
        for (int r = 0; r < 64; r++) s += stage[(h * 64 + r) * STAGE_STRIDE + c];
        atomicAdd(&g_colsum[n * S + s0 + c], s);
    }
    // coalesced E store as fp16 (uint2 = 4 halves)
    #pragma unroll
    for (int it = 0; it < 16; it++) {
        int idx = t + it * 256;
        int r = idx >> 5, q = idx & 31;
        float4 f = *(float4*)&stage[r * STAGE_STRIDE + q * 4];
        __half2 h0 = __floats2half2_rn(f.x, f.y);
        __half2 h1 = __floats2half2_rn(f.z, f.w);
        uint2 u;
        u.x = *(uint32_t*)&h0;
        u.y = *(uint32_t*)&h1;
        *(uint2*)&Eo[(size_t)(l0 + r) * S + s0 + q * 4] = u;
    }
}

// ---------------------------------------------------------------------------
// 2) conf = E^2/(rowsum*colsum); rowmax+argmax, colmax (32-row stripes)
// ---------------------------------------------------------------------------
#define CROWS 32
__global__ __launch_bounds__(256) void conf_k(float* __restrict__ conf) {
    const int n = blockIdx.y;
    const int l0 = blockIdx.x * CROWS;
    const int t = threadIdx.x;
    __shared__ float s_val[8];
    __shared__ int   s_arg[8];

    float ic[25], cm[25];
    #pragma unroll
    for (int k = 0; k < 25; k++) {
        ic[k] = 1.0f / g_colsum[n * S + t + k * 256];
        cm[k] = 0.0f;
    }

    for (int r = 0; r < CROWS; r++) {
        const int l = l0 + r;
        const size_t off = ((size_t)n * L + l) * S;
        const float ir = 1.0f / g_rowsum[n * L + l];
        float rmax = 0.0f; int rarg = t;
        #pragma unroll
        for (int k = 0; k < 25; k++) {
            int s = t + k * 256;
            float e = __half2float(g_Eh[off + s]);
            float c = e * e * ir * ic[k];
            conf[off + s] = c;
            cm[k] = fmaxf(cm[k], c);
            if (c > rmax) { rmax = c; rarg = s; }
        }
        #pragma unroll
        for (int o = 16; o; o >>= 1) {
            float ov = __shfl_xor_sync(0xFFFFFFFFu, rmax, o);
            int   oa = __shfl_xor_sync(0xFFFFFFFFu, rarg, o);
            if (ov > rmax) { rmax = ov; rarg = oa; }
        }
        if ((t & 31) == 0) { s_val[t >> 5] = rmax; s_arg[t >> 5] = rarg; }
        __syncthreads();
        if (t == 0) {
            #pragma unroll
            for (int w = 1; w < 8; w++)
                if (s_val[w] > rmax) { rmax = s_val[w]; rarg = s_arg[w]; }
            g_rowmax[n * L + l] = rmax;
            g_rowarg[n * L + l] = rarg;
        }
        __syncthreads();
    }
    #pragma unroll
    for (int k = 0; k < 25; k++)
        atomicMax(&g_colmax[n * S + t + k * 256], __float_as_int(cm[k]));
}

// ---------------------------------------------------------------------------
// 3) sparse final
// ---------------------------------------------------------------------------
__device__ __forceinline__ bool border_ok(int i) {
    int h = i / GRID_W, w = i % GRID_W;
    return (h >= BORDER) && (h < GRID_W - BORDER) && (w >= BORDER) && (w < GRID_W - BORDER);
}
__global__ void final_sparse_k(float* __restrict__ maskp, float* __restrict__ scoresp) {
    int i = blockIdx.x * blockDim.x + threadIdx.x;
    if (i >= NB * L) return;
    int n = i / L, l = i % L;
    float rmax = g_rowmax[i];
    int s = g_rowarg[i];
    if (rmax > THRESH &&
        __float_as_int(rmax) == g_colmax[n * S + s] &&
        border_ok(l) && border_ok(s)) {
        size_t off = ((size_t)n * L + l) * S + s;
        maskp[off] = 1.0f;
        scoresp[off] = rmax;
    }
}

// ---------------------------------------------------------------------------
extern "C" void kernel_launch(void* const* d_in, const int* in_sizes, int n_in,
                              void* d_out, int out_size) {
    const float* x0 = (const float*)d_in[0];
    const float* x1 = (const float*)d_in[1];

    float* conf    = (float*)d_out;          // [NB, L, S]
    float* maskp   = conf + NLS;             // [NB, L, S]
    float* scoresp = conf + 2 * NLS;         // [NB, L, S]

    cudaFuncSetAttribute(gemm_exp_k, cudaFuncAttributeMaxDynamicSharedMemorySize, SMEM_BYTES);

    cvt_k<<<(2 * CVT_CHUNKS + 255) / 256, 256>>>((const float4*)x0, (const float4*)x1);
    gemm_exp_k<<<dim3(S / BN, L / BM, NB), 256, SMEM_BYTES>>>();
    conf_k<<<dim3(L / CROWS, NB), 256>>>(conf);
    cudaMemsetAsync(maskp, 0, (size_t)2 * NLS * sizeof(float));
    final_sparse_k<<<(NB * L + 255) / 256, 256>>>(maskp, scoresp);
}

// round 8
// speedup vs baseline: 1.6070x; 1.6070x over previous
#include <cuda_runtime.h>
#include <cuda_fp16.h>
#include <mma.h>
#include <cstdint>
using namespace nvcuda;

#define NB 2
#define L 6400
#define S 6400
#define C 256
#define GRID_W 80
#define BORDER 2

static constexpr float SIM_SCALE = 1.0f / 25.6f;   // 1/(C*TEMPERATURE)
static constexpr float THRESH = 0.2f;
static constexpr long long NLS = (long long)NB * L * S;

#define BM 128
#define BN 128
#define BK 32
#define NKT (C / BK)            // 8
#define STAGES 3
#define SSTR 48                 // smem half stride (96B rows)
#define STAGE_STRIDE 132        // floats
#define TILE_BYTES ((BM + BN) * SSTR * 2)      // 24576 per stage
#define SMEM_BYTES (STAGES * TILE_BYTES)       // 73728 >= stage overlay (67584)

// ---- small scratch only (large scratch must alias d_out: measured +225us
// penalty for big __device__ statics on this setup) ----
__device__ __align__(16) __half g_h0[NB * L * C];
__device__ __align__(16) __half g_h1[NB * S * C];
__device__ float g_rowsum[NB * L];
__device__ float g_colsum[NB * S];
__device__ float g_rowmax[NB * L];
__device__ int   g_rowarg[NB * L];
__device__ int   g_colmax[NB * S];   // float bits; conf > 0 so int order == float order

// ---------------------------------------------------------------------------
__device__ __forceinline__ uint32_t smem_u32(const void* p) {
    uint32_t a;
    asm("{ .reg .u64 t; cvta.to.shared.u64 t, %1; cvt.u32.u64 %0, t; }" : "=r"(a) : "l"(p));
    return a;
}
__device__ __forceinline__ void cp_async16(uint32_t saddr, const void* gaddr) {
    asm volatile("cp.async.cg.shared.global [%0], [%1], 16;" :: "r"(saddr), "l"(gaddr));
}
#define CP_COMMIT() asm volatile("cp.async.commit_group;" ::: "memory")
#define CP_WAIT(n)  asm volatile("cp.async.wait_group %0;" :: "n"(n) : "memory")

// ---------------------------------------------------------------------------
// 0) float -> half conversion + stats zeroing (fused; runs every replay)
// ---------------------------------------------------------------------------
#define CVT_CHUNKS (NB * L * C / 4)
__global__ __launch_bounds__(256) void cvt_k(const float4* __restrict__ x0,
                                             const float4* __restrict__ x1) {
    int i = blockIdx.x * blockDim.x + threadIdx.x;
    if (i < NB * S) { g_colsum[i] = 0.0f; g_colmax[i] = 0; g_rowsum[i] = 0.0f; }
    if (i < CVT_CHUNKS) {
        float4 v = x0[i];
        __half2* o = (__half2*)g_h0;
        o[2 * i]     = __floats2half2_rn(v.x, v.y);
        o[2 * i + 1] = __floats2half2_rn(v.z, v.w);
    } else if (i < 2 * CVT_CHUNKS) {
        int j = i - CVT_CHUNKS;
        float4 v = x1[j];
        __half2* o = (__half2*)g_h1;
        o[2 * j]     = __floats2half2_rn(v.x, v.y);
        o[2 * j + 1] = __floats2half2_rn(v.z, v.w);
    }
}

// ---------------------------------------------------------------------------
// 1) FP16 WMMA GEMM 128x128, 3-stage cp.async, fused exp + sums; E fp16
//    into the (fp32-sized) scores region of d_out
// ---------------------------------------------------------------------------
__global__ __launch_bounds__(256, 2) void gemm_exp_k(__half* __restrict__ Eh) {
    extern __shared__ char smem[];
    const uint32_t sb = smem_u32(smem);
    float* stage = (float*)smem;        // overlays stage buffers after mainloop

    const int t = threadIdx.x;
    const int wid = t >> 5;
    const int wm = wid >> 2;       // 0..1 -> 64 rows
    const int wn = wid & 3;        // 0..3 -> 32 cols
    const int n = blockIdx.z;
    const int l0 = blockIdx.y * BM, s0 = blockIdx.x * BN;

    const __half* A = g_h0 + (size_t)n * L * C;
    const __half* B = g_h1 + (size_t)n * S * C;
    __half* Eo = Eh + (size_t)n * L * S;

    wmma::fragment<wmma::accumulator, 16, 16, 16, float> acc[4][2];
    #pragma unroll
    for (int i = 0; i < 4; i++)
        #pragma unroll
        for (int j = 0; j < 2; j++)
            wmma::fill_fragment(acc[i][j], 0.0f);

    auto load_tile = [&](int kt) {
        const int k0 = kt * BK;
        const uint32_t st = (kt % STAGES) * TILE_BYTES;
        #pragma unroll
        for (int i = 0; i < 2; i++) {
            int c = t + i * 256;               // 0..511
            int r = c >> 2, u = c & 3;
            uint32_t so = st + (uint32_t)(r * SSTR + u * 8) * 2;
            cp_async16(sb + so, A + (size_t)(l0 + r) * C + k0 + u * 8);
            cp_async16(sb + so + BM * SSTR * 2, B + (size_t)(s0 + r) * C + k0 + u * 8);
        }
        CP_COMMIT();
    };

    load_tile(0);
    load_tile(1);

    for (int kt = 0; kt < NKT; kt++) {
        CP_WAIT(1);
        __syncthreads();
        if (kt + 2 < NKT) load_tile(kt + 2);
        else              CP_COMMIT();

        const __half* Ab = (const __half*)(smem + (kt % STAGES) * TILE_BYTES);
        const __half* Bb = Ab + BM * SSTR;
        #pragma unroll
        for (int ks = 0; ks < BK; ks += 16) {
            wmma::fragment<wmma::matrix_a, 16, 16, 16, __half, wmma::row_major> af[4];
            wmma::fragment<wmma::matrix_b, 16, 16, 16, __half, wmma::col_major> bf[2];
            #pragma unroll
            for (int i = 0; i < 4; i++)
                wmma::load_matrix_sync(af[i], Ab + (wm * 64 + i * 16) * SSTR + ks, SSTR);
            #pragma unroll
            for (int j = 0; j < 2; j++)
                wmma::load_matrix_sync(bf[j], Bb + (wn * 32 + j * 16) * SSTR + ks, SSTR);
            #pragma unroll
            for (int i = 0; i < 4; i++)
                #pragma unroll
                for (int j = 0; j < 2; j++)
                    wmma::mma_sync(acc[i][j], af[i], bf[j], acc[i][j]);
        }
    }
    __syncthreads();

    // ---- epilogue: exp, stage, row/col partial sums, coalesced fp16 store
    #pragma unroll
    for (int i = 0; i < 4; i++) {
        #pragma unroll
        for (int j = 0; j < 2; j++) {
            #pragma unroll
            for (int e = 0; e < acc[i][j].num_elements; e++)
                acc[i][j].x[e] = __expf(acc[i][j].x[e] * SIM_SCALE);
            wmma::store_matrix_sync(
                &stage[(size_t)(wm * 64 + i * 16) * STAGE_STRIDE + wn * 32 + j * 16],
                acc[i][j], STAGE_STRIDE, wmma::mem_row_major);
        }
    }
    __syncthreads();

    {   // row partial sums
        const int r = t & 127, h = t >> 7;
        float s = 0.0f;
        #pragma unroll 16
        for (int c = 0; c < 64; c++) s += stage[r * STAGE_STRIDE + h * 64 + c];
        atomicAdd(&g_rowsum[n * L + l0 + r], s);
    }
    {   // col partial sums
        const int c = t & 127, h = t >> 7;
        float s = 0.0f;
        #pragma unroll 16
        for (int r = 0; r < 64; r++) s += stage[(h * 64 + r) * STAGE_STRIDE + c];
        atomicAdd(&g_colsum[n * S + s0 + c], s);
    }
    // coalesced E store as fp16 (uint2 = 4 halves per thread)
    #pragma unroll
    for (int it = 0; it < 16; it++) {
        int idx = t + it * 256;
        int r = idx >> 5, q = idx & 31;
        float4 f = *(float4*)&stage[r * STAGE_STRIDE + q * 4];
        __half2 h0 = __floats2half2_rn(f.x, f.y);
        __half2 h1 = __floats2half2_rn(f.z, f.w);
        uint2 u;
        u.x = *(uint32_t*)&h0;
        u.y = *(uint32_t*)&h1;
        *(uint2*)&Eo[(size_t)(l0 + r) * S + s0 + q * 4] = u;
    }
}

// ---------------------------------------------------------------------------
// 2) conf = E^2/(rowsum*colsum); rowmax+argmax, colmax (32-row stripes)
// ---------------------------------------------------------------------------
#define CROWS 32
__global__ __launch_bounds__(256) void conf_k(const __half* __restrict__ Eh,
                                              float* __restrict__ conf) {
    const int n = blockIdx.y;
    const int l0 = blockIdx.x * CROWS;
    const int t = threadIdx.x;
    __shared__ float s_val[8];
    __shared__ int   s_arg[8];

    float ic[25], cm[25];
    #pragma unroll
    for (int k = 0; k < 25; k++) {
        ic[k] = 1.0f / g_colsum[n * S + t + k * 256];
        cm[k] = 0.0f;
    }

    for (int r = 0; r < CROWS; r++) {
        const int l = l0 + r;
        const size_t off = ((size_t)n * L + l) * S;
        const float ir = 1.0f / g_rowsum[n * L + l];
        float rmax = 0.0f; int rarg = t;
        #pragma unroll
        for (int k = 0; k < 25; k++) {
            int s = t + k * 256;
            float e = __half2float(Eh[off + s]);
            float c = e * e * ir * ic[k];
            conf[off + s] = c;
            cm[k] = fmaxf(cm[k], c);
            if (c > rmax) { rmax = c; rarg = s; }
        }
        #pragma unroll
        for (int o = 16; o; o >>= 1) {
            float ov = __shfl_xor_sync(0xFFFFFFFFu, rmax, o);
            int   oa = __shfl_xor_sync(0xFFFFFFFFu, rarg, o);
            if (ov > rmax) { rmax = ov; rarg = oa; }
        }
        if ((t & 31) == 0) { s_val[t >> 5] = rmax; s_arg[t >> 5] = rarg; }
        __syncthreads();
        if (t == 0) {
            #pragma unroll
            for (int w = 1; w < 8; w++)
                if (s_val[w] > rmax) { rmax = s_val[w]; rarg = s_arg[w]; }
            g_rowmax[n * L + l] = rmax;
            g_rowarg[n * L + l] = rarg;
        }
        __syncthreads();
    }
    #pragma unroll
    for (int k = 0; k < 25; k++)
        atomicMax(&g_colmax[n * S + t + k * 256], __float_as_int(cm[k]));
}

// ---------------------------------------------------------------------------
// 3) sparse final
// ---------------------------------------------------------------------------
__device__ __forceinline__ bool border_ok(int i) {
    int h = i / GRID_W, w = i % GRID_W;
    return (h >= BORDER) && (h < GRID_W - BORDER) && (w >= BORDER) && (w < GRID_W - BORDER);
}
__global__ void final_sparse_k(float* __restrict__ maskp, float* __restrict__ scoresp) {
    int i = blockIdx.x * blockDim.x + threadIdx.x;
    if (i >= NB * L) return;
    int n = i / L, l = i % L;
    float rmax = g_rowmax[i];
    int s = g_rowarg[i];
    if (rmax > THRESH &&
        __float_as_int(rmax) == g_colmax[n * S + s] &&
        border_ok(l) && border_ok(s)) {
        size_t off = ((size_t)n * L + l) * S + s;
        maskp[off] = 1.0f;
        scoresp[off] = rmax;
    }
}

// ---------------------------------------------------------------------------
extern "C" void kernel_launch(void* const* d_in, const int* in_sizes, int n_in,
                              void* d_out, int out_size) {
    const float* x0 = (const float*)d_in[0];
    const float* x1 = (const float*)d_in[1];

    float* conf    = (float*)d_out;          // [NB, L, S]
    float* maskp   = conf + NLS;             // [NB, L, S]
    float* scoresp = conf + 2 * NLS;         // [NB, L, S]
    __half* Eh     = (__half*)scoresp;       // fp16 E scratch in scores region
                                             // (164 MB used of 327 MB; consumed
                                             //  by conf_k before the memset)

    cudaFuncSetAttribute(gemm_exp_k, cudaFuncAttributeMaxDynamicSharedMemorySize, SMEM_BYTES);

    cvt_k<<<(2 * CVT_CHUNKS + 255) / 256, 256>>>((const float4*)x0, (const float4*)x1);
    gemm_exp_k<<<dim3(S / BN, L / BM, NB), 256, SMEM_BYTES>>>(Eh);
    conf_k<<<dim3(L / CROWS, NB), 256>>>(Eh, conf);
    cudaMemsetAsync(maskp, 0, (size_t)2 * NLS * sizeof(float));
    final_sparse_k<<<(NB * L + 255) / 256, 256>>>(maskp, scoresp);
}

// round 10
// speedup vs baseline: 1.7292x; 1.0760x over previous
#include <cuda_runtime.h>
#include <cuda_fp16.h>
#include <mma.h>
#include <cstdint>
using namespace nvcuda;

#define NB 2
#define L 6400
#define S 6400
#define C 256
#define GRID_W 80
#define BORDER 2

static constexpr float SIM_SCALE = 1.0f / 25.6f;   // 1/(C*TEMPERATURE)
static constexpr float THRESH = 0.2f;
static constexpr long long NLS = (long long)NB * L * S;

#define BM 128
#define BN 128
#define BK 32
#define NKT (C / BK)            // 8
#define STAGES 3
#define SSTR 48                 // smem half stride (96B rows)
#define STAGE_STRIDE 132        // floats
#define TILE_BYTES ((BM + BN) * SSTR * 2)      // 24576 per stage
#define SMEM_BYTES (STAGES * TILE_BYTES)       // 73728 >= stage overlay (67584)

// ---- small scratch only (large scratch must alias d_out: measured +225us
// penalty for big __device__ statics on this setup) ----
__device__ __align__(16) __half g_h0[NB * L * C];
__device__ __align__(16) __half g_h1[NB * S * C];
__device__ float g_rowsum[NB * L];
__device__ float g_colsum[NB * S];
__device__ float g_rowmax[NB * L];
__device__ int   g_rowarg[NB * L];
__device__ int   g_colmax[NB * S];   // float bits; conf > 0 so int order == float order

// ---------------------------------------------------------------------------
__device__ __forceinline__ uint32_t smem_u32(const void* p) {
    uint32_t a;
    asm("{ .reg .u64 t; cvta.to.shared.u64 t, %1; cvt.u32.u64 %0, t; }" : "=r"(a) : "l"(p));
    return a;
}
__device__ __forceinline__ void cp_async16(uint32_t saddr, const void* gaddr) {
    asm volatile("cp.async.cg.shared.global [%0], [%1], 16;" :: "r"(saddr), "l"(gaddr));
}
#define CP_COMMIT() asm volatile("cp.async.commit_group;" ::: "memory")
#define CP_WAIT(n)  asm volatile("cp.async.wait_group %0;" :: "n"(n) : "memory")

// ---------------------------------------------------------------------------
// 0) float -> half conversion + stats zeroing (fused; runs every replay)
// ---------------------------------------------------------------------------
#define CVT_CHUNKS (NB * L * C / 4)
__global__ __launch_bounds__(256) void cvt_k(const float4* __restrict__ x0,
                                             const float4* __restrict__ x1) {
    int i = blockIdx.x * blockDim.x + threadIdx.x;
    if (i < NB * S) { g_colsum[i] = 0.0f; g_colmax[i] = 0; g_rowsum[i] = 0.0f; }
    if (i < CVT_CHUNKS) {
        float4 v = x0[i];
        __half2* o = (__half2*)g_h0;
        o[2 * i]     = __floats2half2_rn(v.x, v.y);
        o[2 * i + 1] = __floats2half2_rn(v.z, v.w);
    } else if (i < 2 * CVT_CHUNKS) {
        int j = i - CVT_CHUNKS;
        float4 v = x1[j];
        __half2* o = (__half2*)g_h1;
        o[2 * j]     = __floats2half2_rn(v.x, v.y);
        o[2 * j + 1] = __floats2half2_rn(v.z, v.w);
    }
}

// ---------------------------------------------------------------------------
// 1) FP16 WMMA GEMM: 128x128 CTA tile, 4 warps x 64x64 warp tiles,
//    3-stage cp.async, fused exp + row/col sums; E fp16 into scores region
// ---------------------------------------------------------------------------
__global__ __launch_bounds__(128) void gemm_exp_k(__half* __restrict__ Eh) {
    extern __shared__ char smem[];
    const uint32_t sb = smem_u32(smem);
    float* stage = (float*)smem;        // overlays stage buffers after mainloop

    const int t = threadIdx.x;
    const int wid = t >> 5;
    const int wm = wid >> 1;       // 0..1 -> 64-row band
    const int wn = wid & 1;        // 0..1 -> 64-col band
    const int n = blockIdx.z;
    const int l0 = blockIdx.y * BM, s0 = blockIdx.x * BN;

    const __half* A = g_h0 + (size_t)n * L * C;
    const __half* B = g_h1 + (size_t)n * S * C;
    __half* Eo = Eh + (size_t)n * L * S;

    wmma::fragment<wmma::accumulator, 16, 16, 16, float> acc[4][4];
    #pragma unroll
    for (int i = 0; i < 4; i++)
        #pragma unroll
        for (int j = 0; j < 4; j++)
            wmma::fill_fragment(acc[i][j], 0.0f);

    // tile loader: A 128x32 + B 128x32 = 1024 16B-chunks, 8 per thread
    auto load_tile = [&](int kt) {
        const int k0 = kt * BK;
        const uint32_t st = (kt % STAGES) * TILE_BYTES;
        #pragma unroll
        for (int i = 0; i < 4; i++) {
            int c = t + i * 128;               // 0..511
            int r = c >> 2, u = c & 3;
            uint32_t so = st + (uint32_t)(r * SSTR + u * 8) * 2;
            cp_async16(sb + so, A + (size_t)(l0 + r) * C + k0 + u * 8);
            cp_async16(sb + so + BM * SSTR * 2, B + (size_t)(s0 + r) * C + k0 + u * 8);
        }
        CP_COMMIT();
    };

    load_tile(0);
    load_tile(1);

    for (int kt = 0; kt < NKT; kt++) {
        CP_WAIT(1);
        __syncthreads();
        if (kt + 2 < NKT) load_tile(kt + 2);
        else              CP_COMMIT();

        const __half* Ab = (const __half*)(smem + (kt % STAGES) * TILE_BYTES);
        const __half* Bb = Ab + BM * SSTR;
        #pragma unroll
        for (int ks = 0; ks < BK; ks += 16) {
            wmma::fragment<wmma::matrix_a, 16, 16, 16, __half, wmma::row_major> af[4];
            wmma::fragment<wmma::matrix_b, 16, 16, 16, __half, wmma::col_major> bf[4];
            #pragma unroll
            for (int i = 0; i < 4; i++)
                wmma::load_matrix_sync(af[i], Ab + (wm * 64 + i * 16) * SSTR + ks, SSTR);
            #pragma unroll
            for (int j = 0; j < 4; j++)
                wmma::load_matrix_sync(bf[j], Bb + (wn * 64 + j * 16) * SSTR + ks, SSTR);
            #pragma unroll
            for (int i = 0; i < 4; i++)
                #pragma unroll
                for (int j = 0; j < 4; j++)
                    wmma::mma_sync(acc[i][j], af[i], bf[j], acc[i][j]);
        }
    }
    __syncthreads();

    // ---- epilogue: exp, stage, row/col partial sums, coalesced fp16 store
    #pragma unroll
    for (int i = 0; i < 4; i++) {
        #pragma unroll
        for (int j = 0; j < 4; j++) {
            #pragma unroll
            for (int e = 0; e < acc[i][j].num_elements; e++)
                acc[i][j].x[e] = __expf(acc[i][j].x[e] * SIM_SCALE);
            wmma::store_matrix_sync(
                &stage[(size_t)(wm * 64 + i * 16) * STAGE_STRIDE + wn * 64 + j * 16],
                acc[i][j], STAGE_STRIDE, wmma::mem_row_major);
        }
    }
    __syncthreads();

    {   // row partial sums: thread t -> full row t (128 floats)
        float s = 0.0f;
        #pragma unroll 16
        for (int c = 0; c < 128; c++) s += stage[t * STAGE_STRIDE + c];
        atomicAdd(&g_rowsum[n * L + l0 + t], s);
    }
    {   // col partial sums: thread t -> full col t (conflict-free: consecutive t)
        float s = 0.0f;
        #pragma unroll 16
        for (int r = 0; r < 128; r++) s += stage[r * STAGE_STRIDE + t];
        atomicAdd(&g_colsum[n * S + s0 + t], s);
    }
    // coalesced E store as fp16 (uint2 = 4 halves per thread, 32 iters)
    #pragma unroll
    for (int it = 0; it < 32; it++) {
        int idx = t + it * 128;
        int r = idx >> 5, q = idx & 31;
        float4 f = *(float4*)&stage[r * STAGE_STRIDE + q * 4];
        __half2 h0 = __floats2half2_rn(f.x, f.y);
        __half2 h1 = __floats2half2_rn(f.z, f.w);
        uint2 u;
        u.x = *(uint32_t*)&h0;
        u.y = *(uint32_t*)&h1;
        *(uint2*)&Eo[(size_t)(l0 + r) * S + s0 + q * 4] = u;
    }
}

// ---------------------------------------------------------------------------
// 2) conf = E^2/(rowsum*colsum); rowmax+argmax, colmax (32-row stripes)
// ---------------------------------------------------------------------------
#define CROWS 32
__global__ __launch_bounds__(256) void conf_k(const __half* __restrict__ Eh,
                                              float* __restrict__ conf) {
    const int n = blockIdx.y;
    const int l0 = blockIdx.x * CROWS;
    const int t = threadIdx.x;
    __shared__ float s_val[8];
    __shared__ int   s_arg[8];

    float ic[25], cm[25];
    #pragma unroll
    for (int k = 0; k < 25; k++) {
        ic[k] = 1.0f / g_colsum[n * S + t + k * 256];
        cm[k] = 0.0f;
    }

    for (int r = 0; r < CROWS; r++) {
        const int l = l0 + r;
        const size_t off = ((size_t)n * L + l) * S;
        const float ir = 1.0f / g_rowsum[n * L + l];
        float rmax = 0.0f; int rarg = t;
        #pragma unroll
        for (int k = 0; k < 25; k++) {
            int s = t + k * 256;
            float e = __half2float(Eh[off + s]);
            float c = e * e * ir * ic[k];
            conf[off + s] = c;
            cm[k] = fmaxf(cm[k], c);
            if (c > rmax) { rmax = c; rarg = s; }
        }
        #pragma unroll
        for (int o = 16; o; o >>= 1) {
            float ov = __shfl_xor_sync(0xFFFFFFFFu, rmax, o);
            int   oa = __shfl_xor_sync(0xFFFFFFFFu, rarg, o);
            if (ov > rmax) { rmax = ov; rarg = oa; }
        }
        if ((t & 31) == 0) { s_val[t >> 5] = rmax; s_arg[t >> 5] = rarg; }
        __syncthreads();
        if (t == 0) {
            #pragma unroll
            for (int w = 1; w < 8; w++)
                if (s_val[w] > rmax) { rmax = s_val[w]; rarg = s_arg[w]; }
            g_rowmax[n * L + l] = rmax;
            g_rowarg[n * L + l] = rarg;
        }
        __syncthreads();
    }
    #pragma unroll
    for (int k = 0; k < 25; k++)
        atomicMax(&g_colmax[n * S + t + k * 256], __float_as_int(cm[k]));
}

// ---------------------------------------------------------------------------
// 3) dense final: writes full mask + scores rows (replaces memset + sparse)
// ---------------------------------------------------------------------------
__device__ __forceinline__ bool border_ok(int i) {
    int h = i / GRID_W, w = i % GRID_W;
    return (h >= BORDER) && (h < GRID_W - BORDER) && (w >= BORDER) && (w < GRID_W - BORDER);
}
__global__ __launch_bounds__(256) void final_dense_k(float* __restrict__ maskp,
                                                     float* __restrict__ scoresp) {
    const int n = blockIdx.y, l = blockIdx.x;
    const int t = threadIdx.x;
    const size_t off = ((size_t)n * L + l) * S;
    const float rmax = g_rowmax[n * L + l];
    const int rarg = g_rowarg[n * L + l];
    // row-level condition (s-independent parts)
    const bool rcond = (rmax > THRESH) && border_ok(l) &&
                       (__float_as_int(rmax) == g_colmax[n * S + rarg]) &&
                       border_ok(rarg);
    #pragma unroll
    for (int k = 0; k < 25; k++) {
        int s = t + k * 256;
        bool m = rcond && (s == rarg);
        maskp[off + s]   = m ? 1.0f : 0.0f;
        scoresp[off + s] = m ? rmax : 0.0f;
    }
}

// ---------------------------------------------------------------------------
extern "C" void kernel_launch(void* const* d_in, const int* in_sizes, int n_in,
                              void* d_out, int out_size) {
    const float* x0 = (const float*)d_in[0];
    const float* x1 = (const float*)d_in[1];

    float* conf    = (float*)d_out;          // [NB, L, S]
    float* maskp   = conf + NLS;             // [NB, L, S]
    float* scoresp = conf + 2 * NLS;         // [NB, L, S]
    __half* Eh     = (__half*)scoresp;       // fp16 E scratch in scores region
                                             // (consumed by conf_k before
                                             //  final_dense_k overwrites)

    cudaFuncSetAttribute(gemm_exp_k, cudaFuncAttributeMaxDynamicSharedMemorySize, SMEM_BYTES);

    cvt_k<<<(2 * CVT_CHUNKS + 255) / 256, 256>>>((const float4*)x0, (const float4*)x1);
    gemm_exp_k<<<dim3(S / BN, L / BM, NB), 128, SMEM_BYTES>>>(Eh);
    conf_k<<<dim3(L / CROWS, NB), 256>>>(Eh, conf);
    final_dense_k<<<dim3(L, NB), 256>>>(maskp, scoresp);
}

// round 11
// speedup vs baseline: 1.7399x; 1.0062x over previous
#include <cuda_runtime.h>
#include <cuda_fp16.h>
#include <mma.h>
#include <cstdint>
using namespace nvcuda;

#define NB 2
#define L 6400
#define S 6400
#define C 256
#define GRID_W 80
#define BORDER 2

static constexpr float SIM_SCALE = 1.0f / 25.6f;   // 1/(C*TEMPERATURE)
static constexpr float THRESH = 0.2f;
static constexpr long long NLS = (long long)NB * L * S;

#define BM 128
#define BN 128
#define BK 32
#define NKT (C / BK)            // 8
#define STAGES 3
#define SSTR 48                 // smem half stride (96B rows)
#define STAGE_STRIDE 132        // floats
#define TILE_BYTES ((BM + BN) * SSTR * 2)      // 24576 per stage
#define SMEM_BYTES (STAGES * TILE_BYTES)       // 73728 >= stage overlay (67584)

// ---- small scratch only (large scratch must alias d_out: measured +225us
// penalty for big __device__ statics on this setup) ----
__device__ __align__(16) __half g_h0[NB * L * C];
__device__ __align__(16) __half g_h1[NB * S * C];
__device__ float g_rowsum[NB * L];
__device__ float g_colsum[NB * S];
__device__ float g_rowmax[NB * L];
__device__ int   g_rowarg[NB * L];
__device__ int   g_colmax[NB * S];   // float bits; conf > 0 so int order == float order

// ---------------------------------------------------------------------------
__device__ __forceinline__ uint32_t smem_u32(const void* p) {
    uint32_t a;
    asm("{ .reg .u64 t; cvta.to.shared.u64 t, %1; cvt.u32.u64 %0, t; }" : "=r"(a) : "l"(p));
    return a;
}
__device__ __forceinline__ void cp_async16(uint32_t saddr, const void* gaddr) {
    asm volatile("cp.async.cg.shared.global [%0], [%1], 16;" :: "r"(saddr), "l"(gaddr));
}
#define CP_COMMIT() asm volatile("cp.async.commit_group;" ::: "memory")
#define CP_WAIT(n)  asm volatile("cp.async.wait_group %0;" :: "n"(n) : "memory")

// ---------------------------------------------------------------------------
// 0) float -> half conversion + stats zeroing (fused; runs every replay)
// ---------------------------------------------------------------------------
#define CVT_CHUNKS (NB * L * C / 4)
__global__ __launch_bounds__(256) void cvt_k(const float4* __restrict__ x0,
                                             const float4* __restrict__ x1) {
    int i = blockIdx.x * blockDim.x + threadIdx.x;
    if (i < NB * S) { g_colsum[i] = 0.0f; g_colmax[i] = 0; g_rowsum[i] = 0.0f; }
    if (i < CVT_CHUNKS) {
        float4 v = x0[i];
        __half2* o = (__half2*)g_h0;
        o[2 * i]     = __floats2half2_rn(v.x, v.y);
        o[2 * i + 1] = __floats2half2_rn(v.z, v.w);
    } else if (i < 2 * CVT_CHUNKS) {
        int j = i - CVT_CHUNKS;
        float4 v = x1[j];
        __half2* o = (__half2*)g_h1;
        o[2 * j]     = __floats2half2_rn(v.x, v.y);
        o[2 * j + 1] = __floats2half2_rn(v.z, v.w);
    }
}

// ---------------------------------------------------------------------------
// 1) FP16 WMMA GEMM: 128x128 CTA tile, 4 warps x 64x64 warp tiles,
//    3-stage cp.async, 3 CTAs/SM, fused exp + row/col sums; E fp16
// ---------------------------------------------------------------------------
__global__ __launch_bounds__(128, 3) void gemm_exp_k(__half* __restrict__ Eh) {
    extern __shared__ char smem[];
    const uint32_t sb = smem_u32(smem);
    float* stage = (float*)smem;        // overlays stage buffers after mainloop

    const int t = threadIdx.x;
    const int wid = t >> 5;
    const int wm = wid >> 1;       // 0..1 -> 64-row band
    const int wn = wid & 1;        // 0..1 -> 64-col band
    const int n = blockIdx.z;
    const int l0 = blockIdx.y * BM, s0 = blockIdx.x * BN;

    const __half* A = g_h0 + (size_t)n * L * C;
    const __half* B = g_h1 + (size_t)n * S * C;
    __half* Eo = Eh + (size_t)n * L * S;

    wmma::fragment<wmma::accumulator, 16, 16, 16, float> acc[4][4];
    #pragma unroll
    for (int i = 0; i < 4; i++)
        #pragma unroll
        for (int j = 0; j < 4; j++)
            wmma::fill_fragment(acc[i][j], 0.0f);

    // tile loader: A 128x32 + B 128x32 = 1024 16B-chunks, 8 per thread
    auto load_tile = [&](int kt) {
        const int k0 = kt * BK;
        const uint32_t st = (kt % STAGES) * TILE_BYTES;
        #pragma unroll
        for (int i = 0; i < 4; i++) {
            int c = t + i * 128;               // 0..511
            int r = c >> 2, u = c & 3;
            uint32_t so = st + (uint32_t)(r * SSTR + u * 8) * 2;
            cp_async16(sb + so, A + (size_t)(l0 + r) * C + k0 + u * 8);
            cp_async16(sb + so + BM * SSTR * 2, B + (size_t)(s0 + r) * C + k0 + u * 8);
        }
        CP_COMMIT();
    };

    load_tile(0);
    load_tile(1);

    for (int kt = 0; kt < NKT; kt++) {
        CP_WAIT(1);
        __syncthreads();
        if (kt + 2 < NKT) load_tile(kt + 2);
        else              CP_COMMIT();

        const __half* Ab = (const __half*)(smem + (kt % STAGES) * TILE_BYTES);
        const __half* Bb = Ab + BM * SSTR;
        #pragma unroll
        for (int ks = 0; ks < BK; ks += 16) {
            wmma::fragment<wmma::matrix_a, 16, 16, 16, __half, wmma::row_major> af[4];
            wmma::fragment<wmma::matrix_b, 16, 16, 16, __half, wmma::col_major> bf[4];
            #pragma unroll
            for (int i = 0; i < 4; i++)
                wmma::load_matrix_sync(af[i], Ab + (wm * 64 + i * 16) * SSTR + ks, SSTR);
            #pragma unroll
            for (int j = 0; j < 4; j++)
                wmma::load_matrix_sync(bf[j], Bb + (wn * 64 + j * 16) * SSTR + ks, SSTR);
            #pragma unroll
            for (int i = 0; i < 4; i++)
                #pragma unroll
                for (int j = 0; j < 4; j++)
                    wmma::mma_sync(acc[i][j], af[i], bf[j], acc[i][j]);
        }
    }
    __syncthreads();

    // ---- epilogue: exp, stage, row/col partial sums, coalesced fp16 store
    #pragma unroll
    for (int i = 0; i < 4; i++) {
        #pragma unroll
        for (int j = 0; j < 4; j++) {
            #pragma unroll
            for (int e = 0; e < acc[i][j].num_elements; e++)
                acc[i][j].x[e] = __expf(acc[i][j].x[e] * SIM_SCALE);
            wmma::store_matrix_sync(
                &stage[(size_t)(wm * 64 + i * 16) * STAGE_STRIDE + wn * 64 + j * 16],
                acc[i][j], STAGE_STRIDE, wmma::mem_row_major);
        }
    }
    __syncthreads();

    {   // row partial sums: thread t -> full row t (128 floats)
        float s = 0.0f;
        #pragma unroll 16
        for (int c = 0; c < 128; c++) s += stage[t * STAGE_STRIDE + c];
        atomicAdd(&g_rowsum[n * L + l0 + t], s);
    }
    {   // col partial sums: thread t -> full col t (conflict-free: consecutive t)
        float s = 0.0f;
        #pragma unroll 16
        for (int r = 0; r < 128; r++) s += stage[r * STAGE_STRIDE + t];
        atomicAdd(&g_colsum[n * S + s0 + t], s);
    }
    // coalesced E store as fp16 (uint2 = 4 halves per thread, 32 iters)
    #pragma unroll
    for (int it = 0; it < 32; it++) {
        int idx = t + it * 128;
        int r = idx >> 5, q = idx & 31;
        float4 f = *(float4*)&stage[r * STAGE_STRIDE + q * 4];
        __half2 h0 = __floats2half2_rn(f.x, f.y);
        __half2 h1 = __floats2half2_rn(f.z, f.w);
        uint2 u;
        u.x = *(uint32_t*)&h0;
        u.y = *(uint32_t*)&h1;
        *(uint2*)&Eo[(size_t)(l0 + r) * S + s0 + q * 4] = u;
    }
}

// ---------------------------------------------------------------------------
// 2) conf = E^2/(rowsum*colsum); rowmax+argmax, colmax (32-row stripes)
// ---------------------------------------------------------------------------
#define CROWS 32
__global__ __launch_bounds__(256) void conf_k(const __half* __restrict__ Eh,
                                              float* __restrict__ conf) {
    const int n = blockIdx.y;
    const int l0 = blockIdx.x * CROWS;
    const int t = threadIdx.x;
    __shared__ float s_val[8];
    __shared__ int   s_arg[8];

    float ic[25], cm[25];
    #pragma unroll
    for (int k = 0; k < 25; k++) {
        ic[k] = 1.0f / g_colsum[n * S + t + k * 256];
        cm[k] = 0.0f;
    }

    for (int r = 0; r < CROWS; r++) {
        const int l = l0 + r;
        const size_t off = ((size_t)n * L + l) * S;
        const float ir = 1.0f / g_rowsum[n * L + l];
        float rmax = 0.0f; int rarg = t;
        #pragma unroll
        for (int k = 0; k < 25; k++) {
            int s = t + k * 256;
            float e = __half2float(Eh[off + s]);
            float c = e * e * ir * ic[k];
            conf[off + s] = c;
            cm[k] = fmaxf(cm[k], c);
            if (c > rmax) { rmax = c; rarg = s; }
        }
        #pragma unroll
        for (int o = 16; o; o >>= 1) {
            float ov = __shfl_xor_sync(0xFFFFFFFFu, rmax, o);
            int   oa = __shfl_xor_sync(0xFFFFFFFFu, rarg, o);
            if (ov > rmax) { rmax = ov; rarg = oa; }
        }
        if ((t & 31) == 0) { s_val[t >> 5] = rmax; s_arg[t >> 5] = rarg; }
        __syncthreads();
        if (t == 0) {
            #pragma unroll
            for (int w = 1; w < 8; w++)
                if (s_val[w] > rmax) { rmax = s_val[w]; rarg = s_arg[w]; }
            g_rowmax[n * L + l] = rmax;
            g_rowarg[n * L + l] = rarg;
        }
        __syncthreads();
    }
    #pragma unroll
    for (int k = 0; k < 25; k++)
        atomicMax(&g_colmax[n * S + t + k * 256], __float_as_int(cm[k]));
}

// ---------------------------------------------------------------------------
// 3) dense final: writes full mask + scores rows (replaces memset + sparse)
// ---------------------------------------------------------------------------
__device__ __forceinline__ bool border_ok(int i) {
    int h = i / GRID_W, w = i % GRID_W;
    return (h >= BORDER) && (h < GRID_W - BORDER) && (w >= BORDER) && (w < GRID_W - BORDER);
}
__global__ __launch_bounds__(256) void final_dense_k(float* __restrict__ maskp,
                                                     float* __restrict__ scoresp) {
    const int n = blockIdx.y, l = blockIdx.x;
    const int t = threadIdx.x;
    const size_t off = ((size_t)n * L + l) * S;
    const float rmax = g_rowmax[n * L + l];
    const int rarg = g_rowarg[n * L + l];
    // row-level condition (s-independent parts)
    const bool rcond = (rmax > THRESH) && border_ok(l) &&
                       (__float_as_int(rmax) == g_colmax[n * S + rarg]) &&
                       border_ok(rarg);
    #pragma unroll
    for (int k = 0; k < 25; k++) {
        int s = t + k * 256;
        bool m = rcond && (s == rarg);
        maskp[off + s]   = m ? 1.0f : 0.0f;
        scoresp[off + s] = m ? rmax : 0.0f;
    }
}

// ---------------------------------------------------------------------------
extern "C" void kernel_launch(void* const* d_in, const int* in_sizes, int n_in,
                              void* d_out, int out_size) {
    const float* x0 = (const float*)d_in[0];
    const float* x1 = (const float*)d_in[1];

    float* conf    = (float*)d_out;          // [NB, L, S]
    float* maskp   = conf + NLS;             // [NB, L, S]
    float* scoresp = conf + 2 * NLS;         // [NB, L, S]
    __half* Eh     = (__half*)scoresp;       // fp16 E scratch in scores region
                                             // (consumed by conf_k before
                                             //  final_dense_k overwrites)

    cudaFuncSetAttribute(gemm_exp_k, cudaFuncAttributeMaxDynamicSharedMemorySize, SMEM_BYTES);

    cvt_k<<<(2 * CVT_CHUNKS + 255) / 256, 256>>>((const float4*)x0, (const float4*)x1);
    gemm_exp_k<<<dim3(S / BN, L / BM, NB), 128, SMEM_BYTES>>>(Eh);
    conf_k<<<dim3(L / CROWS, NB), 256>>>(Eh, conf);
    final_dense_k<<<dim3(L, NB), 256>>>(maskp, scoresp);
}